// round 2
// baseline (speedup 1.0000x reference)
#include <cuda_runtime.h>
#include <math.h>

// BuildingModule: 3-state RC thermal network, serial scan, B=8192 chains.
// One thread per chain. Key trick: reciprocal state i ~= 1/x tracked
// incrementally via a cubic poly for 2^(-m) (no rcp on the critical path),
// and all coefficients pre-scaled by kl_c so the FMA tree emits the log2
// exponent m_c directly.

#define BATCH   8192
#define TSTEPS  1024
#define CHUNK   8
#define NCHUNK  (TSTEPS / CHUNK)   // 128

struct __align__(32) f8 { float v[8]; };

__device__ __forceinline__ f8 ldg256(const float* p) {
    f8 r;
    asm volatile("ld.global.nc.v8.f32 {%0,%1,%2,%3,%4,%5,%6,%7}, [%8];"
        : "=f"(r.v[0]), "=f"(r.v[1]), "=f"(r.v[2]), "=f"(r.v[3]),
          "=f"(r.v[4]), "=f"(r.v[5]), "=f"(r.v[6]), "=f"(r.v[7])
        : "l"(p));
    return r;
}

__device__ __forceinline__ void stg256(float* p, const float* s) {
    asm volatile("st.global.v8.f32 [%0], {%1,%2,%3,%4,%5,%6,%7,%8};"
        :: "l"(p),
           "f"(s[0]), "f"(s[1]), "f"(s[2]), "f"(s[3]),
           "f"(s[4]), "f"(s[5]), "f"(s[6]), "f"(s[7])
        : "memory");
}

__device__ __forceinline__ float rcpa(float x) {
    float y; asm("rcp.approx.ftz.f32 %0, %1;" : "=f"(y) : "f"(x)); return y;
}
__device__ __forceinline__ float ex2a(float x) {
    float y; asm("ex2.approx.ftz.f32 %0, %1;" : "=f"(y) : "f"(x)); return y;
}

__global__ void __launch_bounds__(64)
bm_kernel(const float* __restrict__ x0g,
          const float* __restrict__ ug,
          const float* __restrict__ lamg,
          float* __restrict__ outg)
{
    const int b = blockIdx.x * 64 + threadIdx.x;

    const float e12 = expf(lamg[0]);
    const float e23 = expf(lamg[1]);
    const float ee0 = expf(lamg[2]),  ee1 = expf(lamg[3]),  ee2 = expf(lamg[4]);
    const float es0 = expf(lamg[5]),  es1 = expf(lamg[6]),  es2 = expf(lamg[7]);
    const float eh0 = expf(lamg[8]),  eh1 = expf(lamg[9]),  eh2 = expf(lamg[10]);
    const float ec0 = expf(lamg[11]), ec1 = expf(lamg[12]), ec2 = expf(lamg[13]);

    // kl_c = (H / C_c) * log2(e): x *= 2^(kl_c * s_c)
    const float kl0 = (float)(60.0 / 10665991.0 * 1.4426950408889634);
    const float kl1 = (float)(60.0 / 27000000.0 * 1.4426950408889634);
    const float kl2 = (float)(60.0 /  7953253.0 * 1.4426950408889634);

    // Coefficients pre-scaled by kl_c so the FMA tree yields m_c directly.
    const float g12_0  =  kl0 * e12;
    const float ng12_1 = -kl1 * e12;
    const float g23_1  =  kl1 * e23;
    const float ng23_2 = -kl2 * e23;
    const float eeK0 = kl0*ee0, eeK1 = kl1*ee1, eeK2 = kl2*ee2;
    const float neeK0 = -eeK0, neeK1 = -eeK1, neeK2 = -eeK2;
    const float esK0 = kl0*es0, esK1 = kl1*es1, esK2 = kl2*es2;
    const float ehK0 = kl0*eh0, ehK1 = kl1*eh1, ehK2 = kl2*eh2;
    const float ecK0 = kl0*ec0, ecK1 = kl1*ec1, ecK2 = kl2*ec2;

    // 2^(-m) ~= 1 + P1*m + P2*m^2 + P3*m^3  (|m| <= ~0.05)
    const float P1 = -0.69314718056f;
    const float P2 =  0.24022650696f;
    const float P3 = -0.05550410866f;

    float x0 = x0g[b * 3 + 0];
    float x1 = x0g[b * 3 + 1];
    float x2 = x0g[b * 3 + 2];
    float i0 = rcpa(x0), i1 = rcpa(x1), i2 = rcpa(x2);
    // one Newton step for full fp32 accuracy of the tracked reciprocal
    i0 = i0 * (2.0f - x0 * i0);
    i1 = i1 * (2.0f - x1 * i1);
    i2 = i2 * (2.0f - x2 * i2);

    const float* up = ug   + (size_t)b * (TSTEPS * 8);
    float*       op = outg + (size_t)b * (TSTEPS * 3);

    f8 A[CHUNK], B[CHUNK];
#pragma unroll
    for (int j = 0; j < CHUNK; j++) A[j] = ldg256(up + j * 8);

// One scan step consuming u-row U (an f8).
#define STEP(U) do {                                                          \
    const float u0 = (U).v[0], u1 = (U).v[1];                                 \
    const float d12 = i0 - i1;                                                \
    const float d23 = i1 - i2;                                                \
    const float p0 = i0 * u0, p1 = i1 * u0, p2 = i2 * u0;                     \
    const float w0 = fmaf(esK0, u1, fmaf(ehK0, (U).v[2], fmaf(ecK0, (U).v[5], neeK0))); \
    const float w1 = fmaf(esK1, u1, fmaf(ehK1, (U).v[3], fmaf(ecK1, (U).v[6], neeK1))); \
    const float w2 = fmaf(esK2, u1, fmaf(ehK2, (U).v[4], fmaf(ecK2, (U).v[7], neeK2))); \
    const float q0 = fmaf(eeK0, p0, w0);                                      \
    const float q1 = fmaf(eeK1, p1, w1);                                      \
    const float q2 = fmaf(eeK2, p2, w2);                                      \
    const float m0 = fmaf(g12_0  * d12, x1, q0);                              \
    const float m1 = fmaf(g23_1  * d23, x2, fmaf(ng12_1 * d12, x0, q1));      \
    const float m2 = fmaf(ng23_2 * d23, x1, q2);                              \
    const float r0 = fmaf(fmaf(fmaf(P3, m0, P2), m0, P1), m0, 1.0f);          \
    const float r1 = fmaf(fmaf(fmaf(P3, m1, P2), m1, P1), m1, 1.0f);          \
    const float r2 = fmaf(fmaf(fmaf(P3, m2, P2), m2, P1), m2, 1.0f);          \
    x0 *= ex2a(m0);  x1 *= ex2a(m1);  x2 *= ex2a(m2);                         \
    i0 *= r0;        i1 *= r1;        i2 *= r2;                               \
} while (0)

// Process one chunk held in buffer BUF for chunk index C.
#define DO_CHUNK(BUF, C) do {                                                 \
    float buf[CHUNK * 3];                                                     \
    {                                                                         \
        const bool m0v = ((C) != 0) && ((BUF)[0].v[0] < 1e-6f);               \
        buf[0] = m0v ? -1.0f : x0;                                            \
        buf[1] = m0v ? -1.0f : x1;                                            \
        buf[2] = m0v ? -1.0f : x2;                                            \
    }                                                                         \
    _Pragma("unroll")                                                         \
    for (int j = 0; j < CHUNK; j++) {                                         \
        STEP((BUF)[j]);                                                       \
        if (j < CHUNK - 1) {                                                  \
            const bool mv = (BUF)[j + 1].v[0] < 1e-6f;                        \
            buf[3*(j+1)+0] = mv ? -1.0f : x0;                                 \
            buf[3*(j+1)+1] = mv ? -1.0f : x1;                                 \
            buf[3*(j+1)+2] = mv ? -1.0f : x2;                                 \
        }                                                                     \
    }                                                                         \
    float* ob = op + (size_t)(C) * (CHUNK * 3);                               \
    stg256(ob +  0, buf +  0);                                                \
    stg256(ob +  8, buf +  8);                                                \
    stg256(ob + 16, buf + 16);                                                \
} while (0)

    for (int c = 0; c < NCHUNK; c += 2) {
        // prefetch chunk c+1 into B (c+1 <= 127 always)
#pragma unroll
        for (int j = 0; j < CHUNK; j++)
            B[j] = ldg256(up + (size_t)(c + 1) * (CHUNK * 8) + j * 8);
        DO_CHUNK(A, c);

        if (c + 2 < NCHUNK) {
#pragma unroll
            for (int j = 0; j < CHUNK; j++)
                A[j] = ldg256(up + (size_t)(c + 2) * (CHUNK * 8) + j * 8);
        }
        DO_CHUNK(B, c + 1);
    }
}

extern "C" void kernel_launch(void* const* d_in, const int* in_sizes, int n_in,
                              void* d_out, int out_size)
{
    const float* x0  = nullptr;
    const float* u   = nullptr;
    const float* lam = nullptr;
    for (int i = 0; i < n_in; i++) {
        if (in_sizes[i] == 14)               lam = (const float*)d_in[i];
        else if (in_sizes[i] == BATCH * 3)   x0  = (const float*)d_in[i];
        else                                 u   = (const float*)d_in[i];
    }
    bm_kernel<<<BATCH / 64, 64>>>(x0, u, lam, (float*)d_out);
}

// round 3
// speedup vs baseline: 2.4902x; 2.4902x over previous
#include <cuda_runtime.h>
#include <math.h>
#include <stdint.h>

// BuildingModule: 3-state RC thermal scan, B=8192 chains x 1023 serial steps.
// One thread per chain, 32 chains per warp, 1 warp per block.
// u staged gmem->smem via cp.async (coalesced, no register footprint);
// outputs staged smem->gmem coalesced. Math chain uses incremental
// reciprocal (cubic poly for 2^-m) and kl-prefolded coefficients.

#define BATCH   8192
#define TSTEPS  1024
#define CHUNK   16
#define NCHUNK  (TSTEPS / CHUNK)        // 64
#define ROWW    132                     // 128 data words + 4 pad (conflict-free)
#define OROWW   52                      // 48 data words + 4 pad
#define USTRIDE (TSTEPS * 8)            // floats per chain in u
#define OSTRIDE (TSTEPS * 3)            // floats per chain in out

__device__ __forceinline__ void cpa16(uint32_t s, const float* g) {
    asm volatile("cp.async.cg.shared.global [%0], [%1], 16;" :: "r"(s), "l"(g));
}
__device__ __forceinline__ void cpa_commit() {
    asm volatile("cp.async.commit_group;" ::: "memory");
}
__device__ __forceinline__ void cpa_wait1() {
    asm volatile("cp.async.wait_group 1;" ::: "memory");
}
__device__ __forceinline__ void cpa_wait0() {
    asm volatile("cp.async.wait_group 0;" ::: "memory");
}
__device__ __forceinline__ float rcpa(float x) {
    float y; asm("rcp.approx.ftz.f32 %0, %1;" : "=f"(y) : "f"(x)); return y;
}
__device__ __forceinline__ float ex2a(float x) {
    float y; asm("ex2.approx.ftz.f32 %0, %1;" : "=f"(y) : "f"(x)); return y;
}

__global__ void __launch_bounds__(32)
bm_kernel(const float* __restrict__ x0g,
          const float* __restrict__ ug,
          const float* __restrict__ lamg,
          float* __restrict__ outg)
{
    __shared__ float ub[2][32 * ROWW];   // u stage, double buffered (33792 B)
    __shared__ float ob[32 * OROWW];     // out stage (6656 B)

    const int lane = threadIdx.x;
    const int b0   = blockIdx.x * 32;

    const float e12 = expf(lamg[0]);
    const float e23 = expf(lamg[1]);
    const float ee0 = expf(lamg[2]),  ee1 = expf(lamg[3]),  ee2 = expf(lamg[4]);
    const float es0 = expf(lamg[5]),  es1 = expf(lamg[6]),  es2 = expf(lamg[7]);
    const float eh0 = expf(lamg[8]),  eh1 = expf(lamg[9]),  eh2 = expf(lamg[10]);
    const float ec0 = expf(lamg[11]), ec1 = expf(lamg[12]), ec2 = expf(lamg[13]);

    const float kl0 = (float)(60.0 / 10665991.0 * 1.4426950408889634);
    const float kl1 = (float)(60.0 / 27000000.0 * 1.4426950408889634);
    const float kl2 = (float)(60.0 /  7953253.0 * 1.4426950408889634);

    const float g12_0  =  kl0 * e12;
    const float ng12_1 = -kl1 * e12;
    const float g23_1  =  kl1 * e23;
    const float ng23_2 = -kl2 * e23;
    const float eeK0 = kl0*ee0, eeK1 = kl1*ee1, eeK2 = kl2*ee2;
    const float neeK0 = -eeK0, neeK1 = -eeK1, neeK2 = -eeK2;
    const float esK0 = kl0*es0, esK1 = kl1*es1, esK2 = kl2*es2;
    const float ehK0 = kl0*eh0, ehK1 = kl1*eh1, ehK2 = kl2*eh2;
    const float ecK0 = kl0*ec0, ecK1 = kl1*ec1, ecK2 = kl2*ec2;

    // 2^(-m) ~= 1 + P1 m + P2 m^2 + P3 m^3  (|m| small)
    const float P1 = -0.69314718056f;
    const float P2 =  0.24022650696f;
    const float P3 = -0.05550410866f;

    const int b = b0 + lane;
    float x0 = x0g[b * 3 + 0];
    float x1 = x0g[b * 3 + 1];
    float x2 = x0g[b * 3 + 2];
    float i0 = rcpa(x0), i1 = rcpa(x1), i2 = rcpa(x2);
    i0 = i0 * (2.0f - x0 * i0);
    i1 = i1 * (2.0f - x1 * i1);
    i2 = i2 * (2.0f - x2 * i2);

    const float* up0 = ug + (size_t)b0 * USTRIDE;   // warp's chain-0 u base

    // Stage chunk c into buffer sb: iteration i = chain i, lanes cover 512B.
    // gmem floats: (b0+i)*USTRIDE + c*CHUNK*8 + lane*4
#define STAGE(C, BI) do {                                                     \
    uint32_t s = (uint32_t)__cvta_generic_to_shared(&ub[BI][lane * 4]);       \
    const float* g = up0 + (size_t)(C) * (CHUNK * 8) + lane * 4;              \
    _Pragma("unroll")                                                         \
    for (int i_ = 0; i_ < 32; i_++) {                                         \
        cpa16(s, g);                                                          \
        s += ROWW * 4;                                                        \
        g += USTRIDE;                                                         \
    }                                                                         \
    cpa_commit();                                                             \
} while (0)

    STAGE(0, 0);
    STAGE(1, 1);
    cpa_wait1();               // chunk 0 resident
    __syncwarp();

    for (int c = 0; c < NCHUNK; c++) {
        const int bi = c & 1;
        const float* row = &ub[bi][lane * ROWW];
        float* orow = &ob[lane * OROWW];

#pragma unroll
        for (int j = 0; j < CHUNK; j++) {
            const float4 ua = *(const float4*)(row + j * 8);      // u0,u1,h0,h1
            const float4 uc = *(const float4*)(row + j * 8 + 4);  // h2,c0,c1,c2

            // out row CHUNK*c + j  <- current state, masked by u0 of this row
            {
                const bool nm = (c == 0) && (j == 0);
                const bool mv = !nm && (ua.x < 1e-6f);
                orow[j * 3 + 0] = mv ? -1.0f : x0;
                orow[j * 3 + 1] = mv ? -1.0f : x1;
                orow[j * 3 + 2] = mv ? -1.0f : x2;
            }

            // scan step consuming this u row
            const float u0 = ua.x, u1 = ua.y;
            const float d12 = i0 - i1;
            const float d23 = i1 - i2;
            const float w0 = fmaf(esK0, u1, fmaf(ehK0, ua.z, fmaf(ecK0, uc.y, neeK0)));
            const float w1 = fmaf(esK1, u1, fmaf(ehK1, ua.w, fmaf(ecK1, uc.z, neeK1)));
            const float w2 = fmaf(esK2, u1, fmaf(ehK2, uc.x, fmaf(ecK2, uc.w, neeK2)));
            const float q0 = fmaf(eeK0, i0 * u0, w0);
            const float q1 = fmaf(eeK1, i1 * u0, w1);
            const float q2 = fmaf(eeK2, i2 * u0, w2);
            const float m0 = fmaf(g12_0  * d12, x1, q0);
            const float m1 = fmaf(g23_1  * d23, x2, fmaf(ng12_1 * d12, x0, q1));
            const float m2 = fmaf(ng23_2 * d23, x1, q2);
            const float r0 = fmaf(fmaf(fmaf(P3, m0, P2), m0, P1), m0, 1.0f);
            const float r1 = fmaf(fmaf(fmaf(P3, m1, P2), m1, P1), m1, 1.0f);
            const float r2 = fmaf(fmaf(fmaf(P3, m2, P2), m2, P1), m2, 1.0f);
            x0 *= ex2a(m0);  x1 *= ex2a(m1);  x2 *= ex2a(m2);
            i0 *= r0;        i1 *= r1;        i2 *= r2;
        }

        // prefetch chunk c+2 into the buffer we just finished consuming
        if (c + 2 < NCHUNK) {
            STAGE(c + 2, bi);
        }

        __syncwarp();   // ob writes visible to all lanes

        // coalesced drain: 32 chains x 48 floats = 384 x 16B units, 12 iters
#pragma unroll
        for (int it = 0; it < 12; it++) {
            const int unit  = it * 32 + lane;
            const int chain = unit / 12;
            const int o     = unit - chain * 12;
            const float4 v = *(const float4*)(&ob[chain * OROWW + o * 4]);
            *(float4*)(outg + (size_t)(b0 + chain) * OSTRIDE + c * (CHUNK * 3) + o * 4) = v;
        }

        if (c + 2 < NCHUNK) cpa_wait1();   // chunk c+1 resident
        else                cpa_wait0();
        __syncwarp();   // staged data visible; ob safe to overwrite
    }
}

extern "C" void kernel_launch(void* const* d_in, const int* in_sizes, int n_in,
                              void* d_out, int out_size)
{
    const float* x0  = nullptr;
    const float* u   = nullptr;
    const float* lam = nullptr;
    for (int i = 0; i < n_in; i++) {
        if (in_sizes[i] == 14)               lam = (const float*)d_in[i];
        else if (in_sizes[i] == BATCH * 3)   x0  = (const float*)d_in[i];
        else                                 u   = (const float*)d_in[i];
    }
    bm_kernel<<<BATCH / 32, 32>>>(x0, u, lam, (float*)d_out);
}